// round 13
// baseline (speedup 1.0000x reference)
#include <cuda_runtime.h>

// Problem constants
#define BATCH   1024
#define TSTEPS  256
#define UNITS   256
#define G4      1024   // 4*UNITS
#define NC      128
#define TB      8                 // batch rows per CTA
#define NCTA    (BATCH / TB)      // 128 CTAs
#define NTHREADS 512              // 16 warps -> 4 warps/SMSP

// smem layout (floats)
#define ZROWP    1036                  // z row pitch: bank-conflict-free gate reads
#define Z_FLOATS (TB * ZROWP)          // 8288
#define HD_FLOATS (UNITS * 16)         // h duplicated: [unit][8 rows x 2 dup] = 4096
#define SMEM_BYTES ((Z_FLOATS + HD_FLOATS) * 4)   // 49536 B -> dynamic smem

typedef unsigned long long u64;

__device__ __forceinline__ void ffma2(u64& d, u64 a, u64 b) {
    asm("fma.rn.f32x2 %0, %1, %2, %0;" : "+l"(d) : "l"(a), "l"(b));
}
__device__ __forceinline__ void unpack2(u64 v, float& lo, float& hi) {
    asm("mov.b64 {%0, %1}, %2;" : "=f"(lo), "=f"(hi) : "l"(v));
}

// ---- numerically safe fast activations (identical to passing versions) ----
__device__ __forceinline__ float sigmoid_f(float x) {
    float e = __expf(-x);
    return __fdividef(1.0f, 1.0f + e);
}
__device__ __forceinline__ float tanh_f(float x) {
    float a = fabsf(x);
    float e = __expf(-2.0f * a);
    float t = 1.0f - __fdividef(2.0f * e, 1.0f + e);
    return copysignf(t, x);
}

__global__ __launch_bounds__(NTHREADS, 1)
void lstm_char_rnn_kernel(const int*   __restrict__ inp,   // [1024,256] int32
                          const float* __restrict__ Wk,    // kernel [128,1024]
                          const float* __restrict__ R,     // recurrent [256,1024]
                          const float* __restrict__ bias,  // [1024]
                          const float* __restrict__ Dw,    // dense_w [256,128]
                          const float* __restrict__ Db,    // dense_b [128]
                          float*       __restrict__ out)   // [1024,128]
{
    extern __shared__ float sm[];
    float* z_s = sm;                 // [8][ZROWP]  z[row][col]; reused for logits
    float* hd  = sm + Z_FLOATS;      // [256][16]: per unit, 8 rows stored DUPLICATED:
                                     //   hd[k*16 + 2r] = hd[k*16 + 2r + 1] = h(k, row r)

    const int t  = threadIdx.x;      // 0..511
    const int b0 = blockIdx.x * TB;

    // matvec tile: thread owns 8 cols x 2 rows
    const int cg = t >> 2;           // 0..127 -> cols j0..j0+7
    const int j0 = 8 * cg;
    const int rg = t & 3;            // -> rows r0, r0+1
    const int r0 = 2 * rg;

    // zero duplicated h state
    for (int i = t; i < HD_FLOATS; i += NTHREADS) hd[i] = 0.0f;

    // gate-phase ownership: thread owns unit u = t>>1, rows 4*(t&1)..+3
    const int u   = t >> 1;
    const int rg0 = 4 * (t & 1);
    const float bi_ = bias[u];
    const float bf_ = bias[UNITS + u];
    const float bg_ = bias[2 * UNITS + u];
    const float bo_ = bias[3 * UNITS + u];

    float c[4];
#pragma unroll
    for (int j = 0; j < 4; j++) c[j] = 0.0f;

    const ulonglong2* R2 = reinterpret_cast<const ulonglong2*>(R);   // 256 u2 per row
    const ulonglong2* W2 = reinterpret_cast<const ulonglong2*>(Wk);  // 256 u2 per row
    const ulonglong2* Rbase = R2 + 2 * cg;

    // prefetch step-0 x_proj gather: rows r0, r0+1, cols j0..j0+7 (no packing!)
    ulonglong2 wa0, wa1, wb0, wb1;
    {
        int v0 = __ldg(&inp[(b0 + r0)     * TSTEPS]);
        int v1 = __ldg(&inp[(b0 + r0 + 1) * TSTEPS]);
        wa0 = __ldg(&W2[v0 * 256 + 2 * cg]);
        wa1 = __ldg(&W2[v0 * 256 + 2 * cg + 1]);
        wb0 = __ldg(&W2[v1 * 256 + 2 * cg]);
        wb1 = __ldg(&W2[v1 * 256 + 2 * cg + 1]);
    }

    __syncthreads();

    for (int step = 0; step < TSTEPS; step++) {
        // ========== matvec: z[r0..r0+1][j0..j0+7] ==========
        // acc[r][q]: f32x2 = (z[r0+r][j0+2q], z[r0+r][j0+2q+1])
        u64 acc[2][4];
        acc[0][0] = wa0.x;  acc[0][1] = wa0.y;  acc[0][2] = wa1.x;  acc[0][3] = wa1.y;
        acc[1][0] = wb0.x;  acc[1][1] = wb0.y;  acc[1][2] = wb1.x;  acc[1][3] = wb1.y;

        {
            const ulonglong2* Rp = Rbase;
            const float*      hp = &hd[4 * rg];
            for (int kk = 0; kk < UNITS; kk += 4) {
                // batch 8 R loads (1KB/warp in flight -> hides L2 latency)
                ulonglong2 ra0 = __ldg(Rp);
                ulonglong2 rb0 = __ldg(Rp + 1);
                ulonglong2 ra1 = __ldg(Rp + 256);
                ulonglong2 rb1 = __ldg(Rp + 257);
                ulonglong2 ra2 = __ldg(Rp + 512);
                ulonglong2 rb2 = __ldg(Rp + 513);
                ulonglong2 ra3 = __ldg(Rp + 768);
                ulonglong2 rb3 = __ldg(Rp + 769);
                Rp += 1024;
                // h duplicated pairs: (h[r0],h[r0]) , (h[r0+1],h[r0+1])
                ulonglong2 h0 = *reinterpret_cast<const ulonglong2*>(hp);
                ulonglong2 h1 = *reinterpret_cast<const ulonglong2*>(hp + 16);
                ulonglong2 h2 = *reinterpret_cast<const ulonglong2*>(hp + 32);
                ulonglong2 h3 = *reinterpret_cast<const ulonglong2*>(hp + 48);
                hp += 64;

                ffma2(acc[0][0], h0.x, ra0.x);  ffma2(acc[0][1], h0.x, ra0.y);
                ffma2(acc[0][2], h0.x, rb0.x);  ffma2(acc[0][3], h0.x, rb0.y);
                ffma2(acc[1][0], h0.y, ra0.x);  ffma2(acc[1][1], h0.y, ra0.y);
                ffma2(acc[1][2], h0.y, rb0.x);  ffma2(acc[1][3], h0.y, rb0.y);

                ffma2(acc[0][0], h1.x, ra1.x);  ffma2(acc[0][1], h1.x, ra1.y);
                ffma2(acc[0][2], h1.x, rb1.x);  ffma2(acc[0][3], h1.x, rb1.y);
                ffma2(acc[1][0], h1.y, ra1.x);  ffma2(acc[1][1], h1.y, ra1.y);
                ffma2(acc[1][2], h1.y, rb1.x);  ffma2(acc[1][3], h1.y, rb1.y);

                ffma2(acc[0][0], h2.x, ra2.x);  ffma2(acc[0][1], h2.x, ra2.y);
                ffma2(acc[0][2], h2.x, rb2.x);  ffma2(acc[0][3], h2.x, rb2.y);
                ffma2(acc[1][0], h2.y, ra2.x);  ffma2(acc[1][1], h2.y, ra2.y);
                ffma2(acc[1][2], h2.y, rb2.x);  ffma2(acc[1][3], h2.y, rb2.y);

                ffma2(acc[0][0], h3.x, ra3.x);  ffma2(acc[0][1], h3.x, ra3.y);
                ffma2(acc[0][2], h3.x, rb3.x);  ffma2(acc[0][3], h3.x, rb3.y);
                ffma2(acc[1][0], h3.y, ra3.x);  ffma2(acc[1][1], h3.y, ra3.y);
                ffma2(acc[1][2], h3.y, rb3.x);  ffma2(acc[1][3], h3.y, rb3.y);
            }
        }

        // prefetch next step's x_proj gather (hides under z-write + gates)
        {
            int s = (step + 1) & (TSTEPS - 1);
            int v0 = __ldg(&inp[(b0 + r0)     * TSTEPS + s]);
            int v1 = __ldg(&inp[(b0 + r0 + 1) * TSTEPS + s]);
            wa0 = __ldg(&W2[v0 * 256 + 2 * cg]);
            wa1 = __ldg(&W2[v0 * 256 + 2 * cg + 1]);
            wb0 = __ldg(&W2[v1 * 256 + 2 * cg]);
            wb1 = __ldg(&W2[v1 * 256 + 2 * cg + 1]);
        }

        // write z (transposed: z[row][col]) — f32x2 = 2 adjacent cols -> contiguous
#pragma unroll
        for (int r = 0; r < 2; r++) {
            float* zr = &z_s[(r0 + r) * ZROWP + j0];
            *reinterpret_cast<u64*>(zr)     = acc[r][0];
            *reinterpret_cast<u64*>(zr + 2) = acc[r][1];
            *reinterpret_cast<u64*>(zr + 4) = acc[r][2];
            *reinterpret_cast<u64*>(zr + 6) = acc[r][3];
        }
        __syncthreads();

        // ========== gates: thread owns unit u, rows rg0..rg0+3 ==========
        float hv[4];
#pragma unroll
        for (int j = 0; j < 4; j++) {
            int r = rg0 + j;
            const float* zr = &z_s[r * ZROWP];
            float zi = zr[u]             + bi_;
            float zf = zr[UNITS + u]     + bf_;
            float zg = zr[2 * UNITS + u] + bg_;
            float zo = zr[3 * UNITS + u] + bo_;
            float ig = sigmoid_f(zi);
            float fg = sigmoid_f(zf);
            float gg = tanh_f(zg);
            float og = sigmoid_f(zo);
            float cn = fg * c[j] + ig * gg;
            c[j] = cn;
            hv[j] = og * tanh_f(cn);
        }
        // write h DUPLICATED: hd[u*16 + 2r] = hd[u*16 + 2r+1] = h
        {
            float4* dst = reinterpret_cast<float4*>(&hd[u * 16 + 2 * rg0]);
            dst[0] = make_float4(hv[0], hv[0], hv[1], hv[1]);
            dst[1] = make_float4(hv[2], hv[2], hv[3], hv[3]);
        }
        __syncthreads();
    }

    // ========== dense: logits[r][jc] = h_last[r] @ Dw + Db ==========
    {
        const int jc = t & (NC - 1);     // output column
        const int rp = t >> 7;           // row pair: rows 2rp, 2rp+1
        float lg0 = __ldg(&Db[jc]);
        float lg1 = lg0;
        const float* hp = &hd[4 * rp];
        for (int uu = 0; uu < UNITS; uu++) {
            float w = __ldg(&Dw[uu * NC + jc]);
            lg0 = fmaf(hp[uu * 16],     w, lg0);
            lg1 = fmaf(hp[uu * 16 + 2], w, lg1);
        }
        __syncthreads();   // hd reads done before z_s region reuse? (separate regions; safe)
        sm[(2 * rp)     * NC + jc] = lg0;
        sm[(2 * rp + 1) * NC + jc] = lg1;
    }
    __syncthreads();

    // ========== softmax: first 8 warps, warp w handles local row w ==========
    if (t < 256) {
        const int w    = t >> 5;
        const int lane = t & 31;
        float v[4];
        float mx = -3.0e38f;
#pragma unroll
        for (int q = 0; q < 4; q++) {
            v[q] = sm[w * NC + lane + 32 * q];
            mx = fmaxf(mx, v[q]);
        }
#pragma unroll
        for (int off = 16; off >= 1; off >>= 1)
            mx = fmaxf(mx, __shfl_xor_sync(0xffffffffu, mx, off));
        float sum = 0.0f;
#pragma unroll
        for (int q = 0; q < 4; q++) { v[q] = __expf(v[q] - mx); sum += v[q]; }
#pragma unroll
        for (int off = 16; off >= 1; off >>= 1)
            sum += __shfl_xor_sync(0xffffffffu, sum, off);
        float inv = 1.0f / sum;
#pragma unroll
        for (int q = 0; q < 4; q++)
            out[(b0 + w) * NC + lane + 32 * q] = v[q] * inv;
    }
}

extern "C" void kernel_launch(void* const* d_in, const int* in_sizes, int n_in,
                              void* d_out, int out_size) {
    const int*   inp  = (const int*)  d_in[0];  // inputs [1024,256]
    const float* Wk   = (const float*)d_in[1];  // kernel [128,1024]
    const float* R    = (const float*)d_in[2];  // recurrent_kernel [256,1024]
    const float* bias = (const float*)d_in[3];  // bias [1024]
    const float* Dw   = (const float*)d_in[4];  // dense_w [256,128]
    const float* Db   = (const float*)d_in[5];  // dense_b [128]
    float*       out  = (float*)d_out;          // [1024,128]

    cudaFuncSetAttribute(lstm_char_rnn_kernel,
                         cudaFuncAttributeMaxDynamicSharedMemorySize, SMEM_BYTES);

    lstm_char_rnn_kernel<<<NCTA, NTHREADS, SMEM_BYTES>>>(inp, Wk, R, bias, Dw, Db, out);
}